// round 1
// baseline (speedup 1.0000x reference)
#include <cuda_runtime.h>
#include <cstdint>
#include <cstddef>

// Problem constants
// bs=8, h=w=32, D=128, HEADS=8, PE=64, MAXP=32
// tokens per batch = 1024, total tokens = 8192
// Q/K per (b,head): [1024 x 128]; scores per query: 1024 keys (32x32)

#define NTOK_ALL 8192

// Scratch (device globals; no allocation allowed)
__device__ float g_x [NTOK_ALL * 128];   // layernormed x, [b][r][c][d]
__device__ float g_xt[NTOK_ALL * 128];   // transposed tokens: g_xt[b][c*32+r] = x[b][r][c]
__device__ float g_q [NTOK_ALL * 1024];  // Q_all[b*1024+t][h*128+d] = xT[b][t] . Wq[h*128+d]
__device__ float g_k [NTOK_ALL * 1024];
__device__ float g_ctx[NTOK_ALL * 1024]; // context [b][u*32+v][h*128+d]

// ---------------------------------------------------------------------------
// LayerNorm: one warp per token, writes normal + transposed copies
// ---------------------------------------------------------------------------
__global__ __launch_bounds__(256) void ln_kernel(const float* __restrict__ hs,
                                                 const float* __restrict__ gam,
                                                 const float* __restrict__ bet) {
    int warp = threadIdx.x >> 5;
    int lane = threadIdx.x & 31;
    int tok  = (blockIdx.x << 3) + warp;   // 1024 blocks * 8 warps = 8192 tokens

    float4 v = reinterpret_cast<const float4*>(hs)[tok * 32 + lane];
    float s  = v.x + v.y + v.z + v.w;
    float s2 = v.x * v.x + v.y * v.y + v.z * v.z + v.w * v.w;
#pragma unroll
    for (int o = 16; o; o >>= 1) {
        s  += __shfl_xor_sync(0xffffffffu, s,  o);
        s2 += __shfl_xor_sync(0xffffffffu, s2, o);
    }
    float mu   = s * (1.0f / 128.0f);
    float var  = s2 * (1.0f / 128.0f) - mu * mu;
    float rstd = rsqrtf(var + 1e-5f);

    float4 g4 = reinterpret_cast<const float4*>(gam)[lane];
    float4 b4 = reinterpret_cast<const float4*>(bet)[lane];
    float4 y;
    y.x = (v.x - mu) * rstd * g4.x + b4.x;
    y.y = (v.y - mu) * rstd * g4.y + b4.y;
    y.z = (v.z - mu) * rstd * g4.z + b4.z;
    y.w = (v.w - mu) * rstd * g4.w + b4.w;

    reinterpret_cast<float4*>(g_x)[tok * 32 + lane] = y;

    int b  = tok >> 10;
    int t  = tok & 1023;                    // t = r*32 + c
    int tt = ((t & 31) << 5) + (t >> 5);    // tt = c*32 + r
    reinterpret_cast<float4*>(g_xt)[(b * 1024 + tt) * 32 + lane] = y;
}

// ---------------------------------------------------------------------------
// Q/K projection: G[row, o] = xT[row] . W[o],  rows = 8192, o = 1024, k = 128
// block: 32 rows x 128 cols; grid (256, 8, 2); z selects Wq/Wk
// ---------------------------------------------------------------------------
__global__ __launch_bounds__(256) void proj_kernel(const float* __restrict__ Wq,
                                                   const float* __restrict__ Wk) {
    extern __shared__ float sm[];
    float* sA = sm;          // 32 * 128
    float* sW = sm + 4096;   // 128 * 129 (padded)

    const float* Wsrc = (blockIdx.z == 0) ? Wq : Wk;
    float* dst        = (blockIdx.z == 0) ? g_q : g_k;
    int row0 = blockIdx.x * 32;
    int cb   = blockIdx.y * 128;
    int tid  = threadIdx.x;

    for (int i = tid; i < 4096; i += 256)
        sA[i] = g_xt[(size_t)(row0 + (i >> 7)) * 128 + (i & 127)];
    for (int i = tid; i < 16384; i += 256) {
        int o = i >> 7, c = i & 127;
        sW[c * 129 + o] = Wsrc[(size_t)(cb + o) * 128 + c];
    }
    __syncthreads();

    int ty = tid >> 5, tx = tid & 31;
    int t0 = ty * 4;
    float acc[4][4] = {};
#pragma unroll 4
    for (int c = 0; c < 128; c++) {
        float av[4], wv[4];
#pragma unroll
        for (int i = 0; i < 4; i++) av[i] = sA[(t0 + i) * 128 + c];
#pragma unroll
        for (int j = 0; j < 4; j++) wv[j] = sW[c * 129 + tx + 32 * j];
#pragma unroll
        for (int i = 0; i < 4; i++)
#pragma unroll
            for (int j = 0; j < 4; j++) acc[i][j] += av[i] * wv[j];
    }
#pragma unroll
    for (int i = 0; i < 4; i++)
#pragma unroll
        for (int j = 0; j < 4; j++)
            dst[(size_t)(row0 + t0 + i) * 1024 + cb + tx + 32 * j] = acc[i][j];
}

// ---------------------------------------------------------------------------
// Fused attention per CTA = (b, h, u): 32 queries (v=0..31) x 1024 keys.
// logits L[v][t=m*32+n] = (q.k + RS(v,n) + CS(v,m)) / sqrt(128)
// softmax over t; write probs; context = P @ x[b]
// ---------------------------------------------------------------------------
#define SQ_OFF  0
#define SK_OFF  4096
#define SRS_OFF 20608
#define SCS_OFF 21632
#define SS_OFF  22656
#define ATTN_SMEM_FLOATS 55424

__global__ __launch_bounds__(256) void attn_kernel(const float* __restrict__ row_emb,
                                                   const float* __restrict__ col_emb,
                                                   float* __restrict__ probs,
                                                   int write_probs) {
    extern __shared__ float sm[];
    float* sQ  = sm + SQ_OFF;    // 32 x 128
    float* sK  = sm + SK_OFF;    // 128 x 129 (K chunk / X chunk, padded)
    float* sRS = sm + SRS_OFF;   // 32 x 32  (row bias per (v,n))
    float* sCS = sm + SCS_OFF;   // 32 x 32  (col bias per (v,m))
    float* sS  = sm + SS_OFF;    // 32 x 1024 logits -> probs

    int u = blockIdx.x, h = blockIdx.y, b = blockIdx.z;
    int tid = threadIdx.x;

    // Q tile: sQ[v][d] = g_q[b*1024 + u*32+v][h*128+d]  (= q[b, v, u, h, d])
    for (int i = tid; i < 4096; i += 256) {
        int v = i >> 7, d = i & 127;
        sQ[i] = g_q[(size_t)(b * 1024 + u * 32 + v) * 1024 + h * 128 + d];
    }
    __syncthreads();

    // Positional biases: RS[v][n] = qrow . row_emb[n-v+31]; CS[v][m] = qcol . col_emb[m-u+31]
    for (int p = tid; p < 1024; p += 256) {
        int v = p >> 5, n = p & 31;
        const float* qv = sQ + v * 128;
        const float* re = row_emb + (n - v + 31) * 64;
        const float* ce = col_emb + (n - u + 31) * 64;   // here n plays role of m
        float srs = 0.f, scs = 0.f;
#pragma unroll 8
        for (int d = 0; d < 64; d++) {
            srs += qv[d]      * re[d];
            scs += qv[64 + d] * ce[d];
        }
        sRS[p] = srs;
        sCS[p] = scs;
    }

    int ty = tid >> 5, tx = tid & 31;
    int v0 = ty * 4;
    const float inv = 0.0883883476483184f; // 1/sqrt(128)

    // Content scores, streamed over 8 key chunks of 128
    for (int kc = 0; kc < 8; kc++) {
        __syncthreads();
        for (int i = tid; i < 16384; i += 256) {
            int key = i >> 7, d = i & 127;
            sK[key * 129 + d] = g_k[(size_t)(b * 1024 + kc * 128 + key) * 1024 + h * 128 + d];
        }
        __syncthreads();
        float acc[4][4] = {};
#pragma unroll 2
        for (int d = 0; d < 128; d++) {
            float qv[4], kv[4];
#pragma unroll
            for (int i = 0; i < 4; i++) qv[i] = sQ[(v0 + i) * 128 + d];
#pragma unroll
            for (int j = 0; j < 4; j++) kv[j] = sK[(tx + 32 * j) * 129 + d];
#pragma unroll
            for (int i = 0; i < 4; i++)
#pragma unroll
                for (int j = 0; j < 4; j++) acc[i][j] += qv[i] * kv[j];
        }
#pragma unroll
        for (int i = 0; i < 4; i++)
#pragma unroll
            for (int j = 0; j < 4; j++) {
                int key = kc * 128 + tx + 32 * j;
                int m = key >> 5, n = key & 31;
                int v = v0 + i;
                sS[v * 1024 + key] = (acc[i][j] + sRS[v * 32 + n] + sCS[v * 32 + m]) * inv;
            }
    }
    __syncthreads();

    // Softmax over 1024 per row; warp ty owns rows v0..v0+3; write probs
    for (int r = 0; r < 4; r++) {
        int v = v0 + r;
        float* rowp = sS + v * 1024;
        float mx = -3.4e38f;
#pragma unroll
        for (int s = 0; s < 32; s++) mx = fmaxf(mx, rowp[tx + 32 * s]);
#pragma unroll
        for (int o = 16; o; o >>= 1) mx = fmaxf(mx, __shfl_xor_sync(0xffffffffu, mx, o));
        float sum = 0.f;
#pragma unroll
        for (int s = 0; s < 32; s++) {
            float e = __expf(rowp[tx + 32 * s] - mx);
            rowp[tx + 32 * s] = e;
            sum += e;
        }
#pragma unroll
        for (int o = 16; o; o >>= 1) sum += __shfl_xor_sync(0xffffffffu, sum, o);
        float rinv = 1.0f / sum;
        float* gp = probs + ((size_t)((b * 32 + u) * 32 + v) * 8 + h) * 1024;
#pragma unroll
        for (int s = 0; s < 32; s++) {
            float pv = rowp[tx + 32 * s] * rinv;
            rowp[tx + 32 * s] = pv;
            if (write_probs) gp[tx + 32 * s] = pv;
        }
    }

    // Context: C[32 x 128] = P (32x1024) @ x[b] (1024x128), streamed over 8 chunks
    float acc2[4][4] = {};
    for (int tc = 0; tc < 8; tc++) {
        __syncthreads();
        for (int i = tid; i < 16384; i += 256) {
            int t = i >> 7, d = i & 127;
            sK[t * 129 + d] = g_x[(size_t)(b * 1024 + tc * 128 + t) * 128 + d];
        }
        __syncthreads();
#pragma unroll 2
        for (int t = 0; t < 128; t++) {
            float pv[4], xv[4];
#pragma unroll
            for (int i = 0; i < 4; i++) pv[i] = sS[(v0 + i) * 1024 + tc * 128 + t];
#pragma unroll
            for (int j = 0; j < 4; j++) xv[j] = sK[t * 129 + tx + 32 * j];
#pragma unroll
            for (int i = 0; i < 4; i++)
#pragma unroll
                for (int j = 0; j < 4; j++) acc2[i][j] += pv[i] * xv[j];
        }
    }
#pragma unroll
    for (int i = 0; i < 4; i++)
#pragma unroll
        for (int j = 0; j < 4; j++)
            g_ctx[(size_t)(b * 1024 + u * 32 + v0 + i) * 1024 + h * 128 + tx + 32 * j] = acc2[i][j];
}

// ---------------------------------------------------------------------------
// Output projection + bias + residual:
// out[row, o] = ctx[row] . Wv[o] + bv[o] + x[row, o]   (rows = 8192, o = 128, k = 1024)
// ---------------------------------------------------------------------------
__global__ __launch_bounds__(256) void outproj_kernel(const float* __restrict__ Wv,
                                                      const float* __restrict__ bias,
                                                      float* __restrict__ out) {
    extern __shared__ float sm[];
    float* sA = sm;          // 32 * 128
    float* sW = sm + 4096;   // 128 * 129
    int row0 = blockIdx.x * 32;
    int tid = threadIdx.x;
    int ty = tid >> 5, tx = tid & 31;
    int t0 = ty * 4;
    float acc[4][4] = {};

    for (int cc = 0; cc < 8; cc++) {
        __syncthreads();
        for (int i = tid; i < 4096; i += 256)
            sA[i] = g_ctx[(size_t)(row0 + (i >> 7)) * 1024 + cc * 128 + (i & 127)];
        for (int i = tid; i < 16384; i += 256) {
            int o = i >> 7, c = i & 127;
            sW[c * 129 + o] = Wv[(size_t)o * 1024 + cc * 128 + c];
        }
        __syncthreads();
#pragma unroll 4
        for (int c = 0; c < 128; c++) {
            float av[4], wv[4];
#pragma unroll
            for (int i = 0; i < 4; i++) av[i] = sA[(t0 + i) * 128 + c];
#pragma unroll
            for (int j = 0; j < 4; j++) wv[j] = sW[c * 129 + tx + 32 * j];
#pragma unroll
            for (int i = 0; i < 4; i++)
#pragma unroll
                for (int j = 0; j < 4; j++) acc[i][j] += av[i] * wv[j];
        }
    }
#pragma unroll
    for (int i = 0; i < 4; i++)
#pragma unroll
        for (int j = 0; j < 4; j++) {
            int o = tx + 32 * j;
            size_t r = (size_t)(row0 + t0 + i);
            out[r * 128 + o] = acc[i][j] + bias[o] + g_x[r * 128 + o];
        }
}

// ---------------------------------------------------------------------------
extern "C" void kernel_launch(void* const* d_in, const int* in_sizes, int n_in,
                              void* d_out, int out_size) {
    const float* hs      = (const float*)d_in[0];
    const float* row_emb = (const float*)d_in[1];
    const float* col_emb = (const float*)d_in[2];
    const float* Wq      = (const float*)d_in[3];
    const float* Wk      = (const float*)d_in[4];
    const float* Wv      = (const float*)d_in[5];
    const float* bv      = (const float*)d_in[6];
    const float* lg      = (const float*)d_in[7];
    const float* lb      = (const float*)d_in[8];

    float* out = (float*)d_out;
    int write_probs = (out_size >= 68157440) ? 1 : 0;
    float* probs = out + 1048576;

    int attn_smem = ATTN_SMEM_FLOATS * 4;     // 221,696 B
    int proj_smem = (4096 + 16512) * 4;       // 82,432 B
    cudaFuncSetAttribute(attn_kernel,    cudaFuncAttributeMaxDynamicSharedMemorySize, attn_smem);
    cudaFuncSetAttribute(proj_kernel,    cudaFuncAttributeMaxDynamicSharedMemorySize, proj_smem);
    cudaFuncSetAttribute(outproj_kernel, cudaFuncAttributeMaxDynamicSharedMemorySize, proj_smem);

    ln_kernel<<<1024, 256>>>(hs, lg, lb);
    proj_kernel<<<dim3(256, 8, 2), 256, proj_smem>>>(Wq, Wk);
    attn_kernel<<<dim3(32, 8, 8), 256, attn_smem>>>(row_emb, col_emb, probs, write_probs);
    outproj_kernel<<<256, 256, proj_smem>>>(Wv, bv, out);
}

// round 2
// speedup vs baseline: 1.4872x; 1.4872x over previous
#include <cuda_runtime.h>
#include <cstdint>
#include <cstddef>

// bs=8, h=w=32, D=128, HEADS=8, PE=64, MAXP=32
#define NTOK_ALL 8192

__device__ float g_x [NTOK_ALL * 128];   // layernormed x, [b][r][c][d]
__device__ float g_xt[NTOK_ALL * 128];   // transposed tokens
__device__ float g_q [NTOK_ALL * 1024];
__device__ float g_k [NTOK_ALL * 1024];
__device__ float g_ctx[NTOK_ALL * 1024];

// ---------------------------------------------------------------------------
// tf32 helpers
// ---------------------------------------------------------------------------
__device__ __forceinline__ unsigned f2tf(float x) {
    unsigned r;
    asm("cvt.rna.tf32.f32 %0, %1;" : "=r"(r) : "f"(x));
    return r;
}
__device__ __forceinline__ void split1(float a, unsigned& hi, unsigned& lo) {
    hi = f2tf(a);
    lo = f2tf(a - __uint_as_float(hi));
}
__device__ __forceinline__ void mma_tf32(float* d, const unsigned* a, const unsigned* b) {
    asm volatile(
        "mma.sync.aligned.m16n8k8.row.col.f32.tf32.tf32.f32 "
        "{%0,%1,%2,%3}, {%4,%5,%6,%7}, {%8,%9}, {%0,%1,%2,%3};"
        : "+f"(d[0]), "+f"(d[1]), "+f"(d[2]), "+f"(d[3])
        : "r"(a[0]), "r"(a[1]), "r"(a[2]), "r"(a[3]), "r"(b[0]), "r"(b[1]));
}

// ---------------------------------------------------------------------------
// LayerNorm
// ---------------------------------------------------------------------------
__global__ __launch_bounds__(256) void ln_kernel(const float* __restrict__ hs,
                                                 const float* __restrict__ gam,
                                                 const float* __restrict__ bet) {
    int warp = threadIdx.x >> 5;
    int lane = threadIdx.x & 31;
    int tok  = (blockIdx.x << 3) + warp;

    float4 v = reinterpret_cast<const float4*>(hs)[tok * 32 + lane];
    float s  = v.x + v.y + v.z + v.w;
    float s2 = v.x * v.x + v.y * v.y + v.z * v.z + v.w * v.w;
#pragma unroll
    for (int o = 16; o; o >>= 1) {
        s  += __shfl_xor_sync(0xffffffffu, s,  o);
        s2 += __shfl_xor_sync(0xffffffffu, s2, o);
    }
    float mu   = s * (1.0f / 128.0f);
    float var  = s2 * (1.0f / 128.0f) - mu * mu;
    float rstd = rsqrtf(var + 1e-5f);

    float4 g4 = reinterpret_cast<const float4*>(gam)[lane];
    float4 b4 = reinterpret_cast<const float4*>(bet)[lane];
    float4 y;
    y.x = (v.x - mu) * rstd * g4.x + b4.x;
    y.y = (v.y - mu) * rstd * g4.y + b4.y;
    y.z = (v.z - mu) * rstd * g4.z + b4.z;
    y.w = (v.w - mu) * rstd * g4.w + b4.w;

    reinterpret_cast<float4*>(g_x)[tok * 32 + lane] = y;

    int b  = tok >> 10;
    int t  = tok & 1023;
    int tt = ((t & 31) << 5) + (t >> 5);
    reinterpret_cast<float4*>(g_xt)[(b * 1024 + tt) * 32 + lane] = y;
}

// ---------------------------------------------------------------------------
// Q/K projection (unchanged scalar GEMM)
// ---------------------------------------------------------------------------
__global__ __launch_bounds__(256) void proj_kernel(const float* __restrict__ Wq,
                                                   const float* __restrict__ Wk) {
    extern __shared__ float sm[];
    float* sA = sm;
    float* sW = sm + 4096;

    const float* Wsrc = (blockIdx.z == 0) ? Wq : Wk;
    float* dst        = (blockIdx.z == 0) ? g_q : g_k;
    int row0 = blockIdx.x * 32;
    int cb   = blockIdx.y * 128;
    int tid  = threadIdx.x;

    for (int i = tid; i < 4096; i += 256)
        sA[i] = g_xt[(size_t)(row0 + (i >> 7)) * 128 + (i & 127)];
    for (int i = tid; i < 16384; i += 256) {
        int o = i >> 7, c = i & 127;
        sW[c * 129 + o] = Wsrc[(size_t)(cb + o) * 128 + c];
    }
    __syncthreads();

    int ty = tid >> 5, tx = tid & 31;
    int t0 = ty * 4;
    float acc[4][4] = {};
#pragma unroll 4
    for (int c = 0; c < 128; c++) {
        float av[4], wv[4];
#pragma unroll
        for (int i = 0; i < 4; i++) av[i] = sA[(t0 + i) * 128 + c];
#pragma unroll
        for (int j = 0; j < 4; j++) wv[j] = sW[c * 129 + tx + 32 * j];
#pragma unroll
        for (int i = 0; i < 4; i++)
#pragma unroll
            for (int j = 0; j < 4; j++) acc[i][j] += av[i] * wv[j];
    }
#pragma unroll
    for (int i = 0; i < 4; i++)
#pragma unroll
        for (int j = 0; j < 4; j++)
            dst[(size_t)(row0 + t0 + i) * 1024 + cb + tx + 32 * j] = acc[i][j];
}

// ---------------------------------------------------------------------------
// Fused attention with tf32x3 tensor-core MMAs.
// CTA = (u, h, b): 32 queries x 1024 keys. 8 warps.
// ---------------------------------------------------------------------------
#define AQ_PITCH 132        // 4 mod 32 -> conflict-free A-frag loads
#define AK_PITCH 132        // 4 mod 32 -> conflict-free B-frag loads [key][d]
#define AX_PITCH 136        // 8 mod 32 -> conflict-free B-frag loads [t][d]
#define AS_PITCH 1028       // 4 mod 32 -> conflict-free P A-frag loads

#define O_SQ   0
#define O_SB   4224                 // 32*132
#define O_SRS  (4224 + 17408)       // sB sized for 128*136
#define O_SCS  (O_SRS + 1024)
#define O_SS   (O_SCS + 1024)
#define ATTN_F (O_SS + 32 * AS_PITCH)   // 56576 floats = 226304 B

__global__ __launch_bounds__(256) void attn_kernel(const float* __restrict__ row_emb,
                                                   const float* __restrict__ col_emb,
                                                   float* __restrict__ probs,
                                                   int write_probs) {
    extern __shared__ float sm[];
    float* sQ  = sm + O_SQ;
    float* sB  = sm + O_SB;
    float* sRS = sm + O_SRS;
    float* sCS = sm + O_SCS;
    float* sS  = sm + O_SS;

    int u = blockIdx.x, h = blockIdx.y, b = blockIdx.z;
    int tid  = threadIdx.x;
    int w    = tid >> 5;
    int lane = tid & 31;
    int grp  = lane >> 2;   // 0..7
    int tig  = lane & 3;    // 0..3

    // Q tile 32x128, pitch 132
    for (int i = tid; i < 1024; i += 256) {
        int v = i >> 5, c4 = (i & 31) << 2;
        float4 q4 = *reinterpret_cast<const float4*>(
            &g_q[(size_t)(b * 1024 + u * 32 + v) * 1024 + h * 128 + c4]);
        *reinterpret_cast<float4*>(&sQ[v * AQ_PITCH + c4]) = q4;
    }
    __syncthreads();

    // Positional biases
    for (int p = tid; p < 1024; p += 256) {
        int v = p >> 5, n = p & 31;
        const float* qv = sQ + v * AQ_PITCH;
        const float* re = row_emb + (n - v + 31) * 64;
        const float* ce = col_emb + (n - u + 31) * 64;
        float srs = 0.f, scs = 0.f;
#pragma unroll 8
        for (int d = 0; d < 64; d++) {
            srs += qv[d]      * re[d];
            scs += qv[64 + d] * ce[d];
        }
        sRS[p] = srs;
        sCS[p] = scs;
    }

    int n0 = w * 16;   // warp's 16-key / 16-col slice
    const float inv = 0.0883883476483184f; // 1/sqrt(128)

    // ---- Scores: S[32 x 1024] = Q K^T via tf32x3, 8 key chunks of 128 ----
    for (int kc = 0; kc < 8; kc++) {
        __syncthreads();
        for (int i = tid; i < 4096; i += 256) {
            int key = i >> 5, c4 = (i & 31) << 2;
            float4 k4 = *reinterpret_cast<const float4*>(
                &g_k[(size_t)(b * 1024 + kc * 128 + key) * 1024 + h * 128 + c4]);
            *reinterpret_cast<float4*>(&sB[key * AK_PITCH + c4]) = k4;
        }
        __syncthreads();

        float acc[2][2][4] = {};
#pragma unroll 4
        for (int k0 = 0; k0 < 128; k0 += 8) {
            unsigned abig[2][4], asml[2][4], bbig[2][2], bsml[2][2];
#pragma unroll
            for (int mt = 0; mt < 2; mt++) {
                int r0 = mt * 16 + grp;
                split1(sQ[r0 * AQ_PITCH + k0 + tig],           abig[mt][0], asml[mt][0]);
                split1(sQ[(r0 + 8) * AQ_PITCH + k0 + tig],     abig[mt][1], asml[mt][1]);
                split1(sQ[r0 * AQ_PITCH + k0 + tig + 4],       abig[mt][2], asml[mt][2]);
                split1(sQ[(r0 + 8) * AQ_PITCH + k0 + tig + 4], abig[mt][3], asml[mt][3]);
            }
#pragma unroll
            for (int nt = 0; nt < 2; nt++) {
                int kr = n0 + nt * 8 + grp;
                split1(sB[kr * AK_PITCH + k0 + tig],     bbig[nt][0], bsml[nt][0]);
                split1(sB[kr * AK_PITCH + k0 + tig + 4], bbig[nt][1], bsml[nt][1]);
            }
#pragma unroll
            for (int mt = 0; mt < 2; mt++)
#pragma unroll
                for (int nt = 0; nt < 2; nt++) {
                    mma_tf32(acc[mt][nt], abig[mt], bbig[nt]);
                    mma_tf32(acc[mt][nt], abig[mt], bsml[nt]);
                    mma_tf32(acc[mt][nt], asml[mt], bbig[nt]);
                }
        }
        // epilogue: add biases, scale, stash logits
#pragma unroll
        for (int mt = 0; mt < 2; mt++)
#pragma unroll
            for (int nt = 0; nt < 2; nt++)
#pragma unroll
                for (int e = 0; e < 4; e++) {
                    int v   = mt * 16 + grp + ((e >= 2) ? 8 : 0);
                    int key = kc * 128 + n0 + nt * 8 + 2 * tig + (e & 1);
                    sS[v * AS_PITCH + key] =
                        (acc[mt][nt][e] + sRS[v * 32 + (key & 31)] + sCS[v * 32 + (key >> 5)]) * inv;
                }
    }
    __syncthreads();

    // ---- Softmax over 1024 per row; warp w owns rows v0..v0+3; write probs ----
    {
        int tx = lane;
        int v0 = w * 4;
        for (int r = 0; r < 4; r++) {
            int v = v0 + r;
            float* rowp = sS + v * AS_PITCH;
            float mx = -3.4e38f;
#pragma unroll
            for (int s = 0; s < 32; s++) mx = fmaxf(mx, rowp[tx + 32 * s]);
#pragma unroll
            for (int o = 16; o; o >>= 1) mx = fmaxf(mx, __shfl_xor_sync(0xffffffffu, mx, o));
            float sum = 0.f;
#pragma unroll
            for (int s = 0; s < 32; s++) {
                float e = __expf(rowp[tx + 32 * s] - mx);
                rowp[tx + 32 * s] = e;
                sum += e;
            }
#pragma unroll
            for (int o = 16; o; o >>= 1) sum += __shfl_xor_sync(0xffffffffu, sum, o);
            float rinv = 1.0f / sum;
            float* gp = probs + ((size_t)((b * 32 + u) * 32 + v) * 8 + h) * 1024;
#pragma unroll
            for (int s = 0; s < 32; s++) {
                float pv = rowp[tx + 32 * s] * rinv;
                rowp[tx + 32 * s] = pv;
                if (write_probs) gp[tx + 32 * s] = pv;
            }
        }
    }

    // ---- Context: C[32 x 128] = P @ x[b] via tf32x3, 8 t-chunks of 128 ----
    float acc2[2][2][4] = {};
    for (int tc = 0; tc < 8; tc++) {
        __syncthreads();   // also orders softmax writes before cross-warp reads
        for (int i = tid; i < 4096; i += 256) {
            int t = i >> 5, c4 = (i & 31) << 2;
            float4 x4 = *reinterpret_cast<const float4*>(
                &g_x[(size_t)(b * 1024 + tc * 128 + t) * 128 + c4]);
            *reinterpret_cast<float4*>(&sB[t * AX_PITCH + c4]) = x4;
        }
        __syncthreads();

#pragma unroll 4
        for (int k0 = 0; k0 < 128; k0 += 8) {
            unsigned abig[2][4], asml[2][4], bbig[2][2], bsml[2][2];
#pragma unroll
            for (int mt = 0; mt < 2; mt++) {
                int r0 = mt * 16 + grp;
                int cb = tc * 128 + k0 + tig;
                split1(sS[r0 * AS_PITCH + cb],           abig[mt][0], asml[mt][0]);
                split1(sS[(r0 + 8) * AS_PITCH + cb],     abig[mt][1], asml[mt][1]);
                split1(sS[r0 * AS_PITCH + cb + 4],       abig[mt][2], asml[mt][2]);
                split1(sS[(r0 + 8) * AS_PITCH + cb + 4], abig[mt][3], asml[mt][3]);
            }
#pragma unroll
            for (int nt = 0; nt < 2; nt++) {
                int col = n0 + nt * 8 + grp;
                split1(sB[(k0 + tig) * AX_PITCH + col],     bbig[nt][0], bsml[nt][0]);
                split1(sB[(k0 + tig + 4) * AX_PITCH + col], bbig[nt][1], bsml[nt][1]);
            }
#pragma unroll
            for (int mt = 0; mt < 2; mt++)
#pragma unroll
                for (int nt = 0; nt < 2; nt++) {
                    mma_tf32(acc2[mt][nt], abig[mt], bbig[nt]);
                    mma_tf32(acc2[mt][nt], abig[mt], bsml[nt]);
                    mma_tf32(acc2[mt][nt], asml[mt], bbig[nt]);
                }
        }
    }
#pragma unroll
    for (int mt = 0; mt < 2; mt++)
#pragma unroll
        for (int nt = 0; nt < 2; nt++)
#pragma unroll
            for (int e = 0; e < 4; e++) {
                int v   = mt * 16 + grp + ((e >= 2) ? 8 : 0);
                int col = n0 + nt * 8 + 2 * tig + (e & 1);
                g_ctx[(size_t)(b * 1024 + u * 32 + v) * 1024 + h * 128 + col] = acc2[mt][nt][e];
            }
}

// ---------------------------------------------------------------------------
// Output projection + bias + residual (unchanged)
// ---------------------------------------------------------------------------
__global__ __launch_bounds__(256) void outproj_kernel(const float* __restrict__ Wv,
                                                      const float* __restrict__ bias,
                                                      float* __restrict__ out) {
    extern __shared__ float sm[];
    float* sA = sm;
    float* sW = sm + 4096;
    int row0 = blockIdx.x * 32;
    int tid = threadIdx.x;
    int ty = tid >> 5, tx = tid & 31;
    int t0 = ty * 4;
    float acc[4][4] = {};

    for (int cc = 0; cc < 8; cc++) {
        __syncthreads();
        for (int i = tid; i < 4096; i += 256)
            sA[i] = g_ctx[(size_t)(row0 + (i >> 7)) * 1024 + cc * 128 + (i & 127)];
        for (int i = tid; i < 16384; i += 256) {
            int o = i >> 7, c = i & 127;
            sW[c * 129 + o] = Wv[(size_t)o * 1024 + cc * 128 + c];
        }
        __syncthreads();
#pragma unroll 4
        for (int c = 0; c < 128; c++) {
            float av[4], wv[4];
#pragma unroll
            for (int i = 0; i < 4; i++) av[i] = sA[(t0 + i) * 128 + c];
#pragma unroll
            for (int j = 0; j < 4; j++) wv[j] = sW[c * 129 + tx + 32 * j];
#pragma unroll
            for (int i = 0; i < 4; i++)
#pragma unroll
                for (int j = 0; j < 4; j++) acc[i][j] += av[i] * wv[j];
        }
    }
#pragma unroll
    for (int i = 0; i < 4; i++)
#pragma unroll
        for (int j = 0; j < 4; j++) {
            int o = tx + 32 * j;
            size_t r = (size_t)(row0 + t0 + i);
            out[r * 128 + o] = acc[i][j] + bias[o] + g_x[r * 128 + o];
        }
}

// ---------------------------------------------------------------------------
extern "C" void kernel_launch(void* const* d_in, const int* in_sizes, int n_in,
                              void* d_out, int out_size) {
    const float* hs      = (const float*)d_in[0];
    const float* row_emb = (const float*)d_in[1];
    const float* col_emb = (const float*)d_in[2];
    const float* Wq      = (const float*)d_in[3];
    const float* Wk      = (const float*)d_in[4];
    const float* Wv      = (const float*)d_in[5];
    const float* bv      = (const float*)d_in[6];
    const float* lg      = (const float*)d_in[7];
    const float* lb      = (const float*)d_in[8];

    float* out = (float*)d_out;
    int write_probs = (out_size >= 68157440) ? 1 : 0;
    float* probs = out + 1048576;

    int attn_smem = ATTN_F * 4;               // 226,304 B
    int proj_smem = (4096 + 16512) * 4;       // 82,432 B
    cudaFuncSetAttribute(attn_kernel,    cudaFuncAttributeMaxDynamicSharedMemorySize, attn_smem);
    cudaFuncSetAttribute(proj_kernel,    cudaFuncAttributeMaxDynamicSharedMemorySize, proj_smem);
    cudaFuncSetAttribute(outproj_kernel, cudaFuncAttributeMaxDynamicSharedMemorySize, proj_smem);

    ln_kernel<<<1024, 256>>>(hs, lg, lb);
    proj_kernel<<<dim3(256, 8, 2), 256, proj_smem>>>(Wq, Wk);
    attn_kernel<<<dim3(32, 8, 8), 256, attn_smem>>>(row_emb, col_emb, probs, write_probs);
    outproj_kernel<<<256, 256, proj_smem>>>(Wv, bv, out);
}

// round 5
// speedup vs baseline: 1.6229x; 1.0913x over previous
#include <cuda_runtime.h>
#include <cuda_bf16.h>
#include <cstdint>
#include <cstddef>

// bs=8, h=w=32, D=128, HEADS=8, PE=64, MAXP=32
#define NTOK_ALL 8192

__device__ float g_x [NTOK_ALL * 128];
__device__ float g_xt[NTOK_ALL * 128];
__device__ float g_q [NTOK_ALL * 1024];
__device__ float g_k [NTOK_ALL * 1024];
__device__ float g_ctx[NTOK_ALL * 1024];

// ---------------------------------------------------------------------------
// helpers
// ---------------------------------------------------------------------------
__device__ __forceinline__ void bsplit(float x, __nv_bfloat16& h, __nv_bfloat16& l) {
    h = __float2bfloat16(x);
    l = __float2bfloat16(x - __bfloat162float(h));
}
__device__ __forceinline__ void mma_bf16(float* d, const unsigned* a, const unsigned* b) {
    asm volatile(
        "mma.sync.aligned.m16n8k16.row.col.f32.bf16.bf16.f32 "
        "{%0,%1,%2,%3}, {%4,%5,%6,%7}, {%8,%9}, {%0,%1,%2,%3};"
        : "+f"(d[0]), "+f"(d[1]), "+f"(d[2]), "+f"(d[3])
        : "r"(a[0]), "r"(a[1]), "r"(a[2]), "r"(a[3]), "r"(b[0]), "r"(b[1]));
}
__device__ __forceinline__ void ldsm_x4(unsigned* r, uint32_t addr) {
    asm volatile("ldmatrix.sync.aligned.m8n8.x4.shared.b16 {%0,%1,%2,%3}, [%4];"
                 : "=r"(r[0]), "=r"(r[1]), "=r"(r[2]), "=r"(r[3]) : "r"(addr));
}
__device__ __forceinline__ void ldsm_x2(unsigned* r, uint32_t addr) {
    asm volatile("ldmatrix.sync.aligned.m8n8.x2.shared.b16 {%0,%1}, [%2];"
                 : "=r"(r[0]), "=r"(r[1]) : "r"(addr));
}
__device__ __forceinline__ void ldsm_x2t(unsigned* r, uint32_t addr) {
    asm volatile("ldmatrix.sync.aligned.m8n8.x2.trans.shared.b16 {%0,%1}, [%2];"
                 : "=r"(r[0]), "=r"(r[1]) : "r"(addr));
}

// ---------------------------------------------------------------------------
// LayerNorm
// ---------------------------------------------------------------------------
__global__ __launch_bounds__(256) void ln_kernel(const float* __restrict__ hs,
                                                 const float* __restrict__ gam,
                                                 const float* __restrict__ bet) {
    int warp = threadIdx.x >> 5;
    int lane = threadIdx.x & 31;
    int tok  = (blockIdx.x << 3) + warp;

    float4 v = reinterpret_cast<const float4*>(hs)[tok * 32 + lane];
    float s  = v.x + v.y + v.z + v.w;
    float s2 = v.x * v.x + v.y * v.y + v.z * v.z + v.w * v.w;
#pragma unroll
    for (int o = 16; o; o >>= 1) {
        s  += __shfl_xor_sync(0xffffffffu, s,  o);
        s2 += __shfl_xor_sync(0xffffffffu, s2, o);
    }
    float mu   = s * (1.0f / 128.0f);
    float var  = s2 * (1.0f / 128.0f) - mu * mu;
    float rstd = rsqrtf(var + 1e-5f);

    float4 g4 = reinterpret_cast<const float4*>(gam)[lane];
    float4 b4 = reinterpret_cast<const float4*>(bet)[lane];
    float4 y;
    y.x = (v.x - mu) * rstd * g4.x + b4.x;
    y.y = (v.y - mu) * rstd * g4.y + b4.y;
    y.z = (v.z - mu) * rstd * g4.z + b4.z;
    y.w = (v.w - mu) * rstd * g4.w + b4.w;

    reinterpret_cast<float4*>(g_x)[tok * 32 + lane] = y;

    int b  = tok >> 10;
    int t  = tok & 1023;
    int tt = ((t & 31) << 5) + (t >> 5);
    reinterpret_cast<float4*>(g_xt)[(b * 1024 + tt) * 32 + lane] = y;
}

// ---------------------------------------------------------------------------
// Q/K projection (scalar)
// ---------------------------------------------------------------------------
__global__ __launch_bounds__(256) void proj_kernel(const float* __restrict__ Wq,
                                                   const float* __restrict__ Wk) {
    extern __shared__ float sm[];
    float* sA = sm;
    float* sW = sm + 4096;

    const float* Wsrc = (blockIdx.z == 0) ? Wq : Wk;
    float* dst        = (blockIdx.z == 0) ? g_q : g_k;
    int row0 = blockIdx.x * 32;
    int cb   = blockIdx.y * 128;
    int tid  = threadIdx.x;

    for (int i = tid; i < 4096; i += 256)
        sA[i] = g_xt[(size_t)(row0 + (i >> 7)) * 128 + (i & 127)];
    for (int i = tid; i < 16384; i += 256) {
        int o = i >> 7, c = i & 127;
        sW[c * 129 + o] = Wsrc[(size_t)(cb + o) * 128 + c];
    }
    __syncthreads();

    int ty = tid >> 5, tx = tid & 31;
    int t0 = ty * 4;
    float acc[4][4] = {};
#pragma unroll 4
    for (int c = 0; c < 128; c++) {
        float av[4], wv[4];
#pragma unroll
        for (int i = 0; i < 4; i++) av[i] = sA[(t0 + i) * 128 + c];
#pragma unroll
        for (int j = 0; j < 4; j++) wv[j] = sW[c * 129 + tx + 32 * j];
#pragma unroll
        for (int i = 0; i < 4; i++)
#pragma unroll
            for (int j = 0; j < 4; j++) acc[i][j] += av[i] * wv[j];
    }
#pragma unroll
    for (int i = 0; i < 4; i++)
#pragma unroll
        for (int j = 0; j < 4; j++)
            dst[(size_t)(row0 + t0 + i) * 1024 + cb + tx + 32 * j] = acc[i][j];
}

// ---------------------------------------------------------------------------
// Fused attention, bf16 hi/lo split + ldmatrix + m16n8k16 MMA
// CTA = (u, h, b): 32 queries x 1024 keys, 8 warps.
// ---------------------------------------------------------------------------
#define O_SQF 0                     // 32 x 132 fp32 Q (for bias dots)
#define O_SQH 4224                  // 32 x 136 bf16 (2176 floats)
#define O_SQL 6400
#define O_SKH 8576                  // 64 x 136 bf16 (4352 floats)  K / X chunk
#define O_SKL 12928
#define O_SPH 17280                 // 32 x 72 bf16 (1152 floats)   P chunk
#define O_SPL 18432
#define O_SRS 19584                 // 32 x 32 fp32
#define O_SCS 20608
#define O_SS  21632                 // 32 x 1028 fp32
#define ATTN_F 54528                // 218,112 bytes

__global__ __launch_bounds__(256) void attn_kernel(const float* __restrict__ row_emb,
                                                   const float* __restrict__ col_emb,
                                                   float* __restrict__ probs,
                                                   int write_probs) {
    extern __shared__ float sm[];
    float*         sQf = sm + O_SQF;
    __nv_bfloat16* sQh = (__nv_bfloat16*)(sm + O_SQH);
    __nv_bfloat16* sQl = (__nv_bfloat16*)(sm + O_SQL);
    __nv_bfloat16* sKh = (__nv_bfloat16*)(sm + O_SKH);
    __nv_bfloat16* sKl = (__nv_bfloat16*)(sm + O_SKL);
    __nv_bfloat16* sPh = (__nv_bfloat16*)(sm + O_SPH);
    __nv_bfloat16* sPl = (__nv_bfloat16*)(sm + O_SPL);
    float* sRS = sm + O_SRS;
    float* sCS = sm + O_SCS;
    float* sS  = sm + O_SS;

    uint32_t aQh = (uint32_t)__cvta_generic_to_shared(sQh);
    uint32_t aQl = (uint32_t)__cvta_generic_to_shared(sQl);
    uint32_t aKh = (uint32_t)__cvta_generic_to_shared(sKh);
    uint32_t aKl = (uint32_t)__cvta_generic_to_shared(sKl);
    uint32_t aPh = (uint32_t)__cvta_generic_to_shared(sPh);
    uint32_t aPl = (uint32_t)__cvta_generic_to_shared(sPl);

    int u = blockIdx.x, h = blockIdx.y, b = blockIdx.z;
    int tid  = threadIdx.x;
    int w    = tid >> 5;
    int lane = tid & 31;
    int grp  = lane >> 2;
    int tig  = lane & 3;

    int rowA = lane & 15;
    int colA = (lane >> 4) << 3;
    int rowB = lane & 7;
    int colB = ((lane >> 3) & 1) << 3;
    int rowT = lane & 15;

    // ---- Load Q tile: fp32 copy + bf16 hi/lo planes ----
    for (int i = tid; i < 1024; i += 256) {
        int v = i >> 5, d4 = (i & 31) << 2;
        float4 q4 = *reinterpret_cast<const float4*>(
            &g_q[(size_t)(b * 1024 + u * 32 + v) * 1024 + h * 128 + d4]);
        *reinterpret_cast<float4*>(&sQf[v * 132 + d4]) = q4;
        __nv_bfloat16 h0, l0, h1, l1, h2, l2, h3, l3;
        bsplit(q4.x, h0, l0); bsplit(q4.y, h1, l1);
        bsplit(q4.z, h2, l2); bsplit(q4.w, h3, l3);
        int o = v * 136 + d4;
        *reinterpret_cast<__nv_bfloat162*>(&sQh[o])     = __nv_bfloat162(h0, h1);
        *reinterpret_cast<__nv_bfloat162*>(&sQh[o + 2]) = __nv_bfloat162(h2, h3);
        *reinterpret_cast<__nv_bfloat162*>(&sQl[o])     = __nv_bfloat162(l0, l1);
        *reinterpret_cast<__nv_bfloat162*>(&sQl[o + 2]) = __nv_bfloat162(l2, l3);
    }
    __syncthreads();

    // ---- Positional biases ----
    for (int p = tid; p < 1024; p += 256) {
        int v = p >> 5, n = p & 31;
        const float* qv = sQf + v * 132;
        const float* re = row_emb + (n - v + 31) * 64;
        const float* ce = col_emb + (n - u + 31) * 64;
        float srs = 0.f, scs = 0.f;
#pragma unroll 8
        for (int d = 0; d < 64; d++) {
            srs += qv[d]      * re[d];
            scs += qv[64 + d] * ce[d];
        }
        sRS[p] = srs;
        sCS[p] = scs;
    }

    int n0 = w << 3;
    const float inv = 0.0883883476483184f;

    // ---- Scores: 16 chunks of 64 keys ----
    for (int kc = 0; kc < 16; kc++) {
        __syncthreads();
        for (int i = tid; i < 2048; i += 256) {
            int key = i >> 5, d4 = (i & 31) << 2;
            float4 k4 = *reinterpret_cast<const float4*>(
                &g_k[(size_t)(b * 1024 + kc * 64 + key) * 1024 + h * 128 + d4]);
            __nv_bfloat16 h0, l0, h1, l1, h2, l2, h3, l3;
            bsplit(k4.x, h0, l0); bsplit(k4.y, h1, l1);
            bsplit(k4.z, h2, l2); bsplit(k4.w, h3, l3);
            int o = key * 136 + d4;
            *reinterpret_cast<__nv_bfloat162*>(&sKh[o])     = __nv_bfloat162(h0, h1);
            *reinterpret_cast<__nv_bfloat162*>(&sKh[o + 2]) = __nv_bfloat162(h2, h3);
            *reinterpret_cast<__nv_bfloat162*>(&sKl[o])     = __nv_bfloat162(l0, l1);
            *reinterpret_cast<__nv_bfloat162*>(&sKl[o + 2]) = __nv_bfloat162(l2, l3);
        }
        __syncthreads();

        float acc[2][4] = {};
#pragma unroll
        for (int k0 = 0; k0 < 128; k0 += 16) {
            unsigned ah[2][4], al[2][4], bh[2], bl[2];
#pragma unroll
            for (int mt = 0; mt < 2; mt++) {
                uint32_t off = (uint32_t)(((mt * 16 + rowA) * 136 + k0 + colA) * 2);
                ldsm_x4(ah[mt], aQh + off);
                ldsm_x4(al[mt], aQl + off);
            }
            uint32_t bo = (uint32_t)(((n0 + rowB) * 136 + k0 + colB) * 2);
            ldsm_x2(bh, aKh + bo);
            ldsm_x2(bl, aKl + bo);
#pragma unroll
            for (int mt = 0; mt < 2; mt++) {
                mma_bf16(acc[mt], ah[mt], bh);
                mma_bf16(acc[mt], ah[mt], bl);
                mma_bf16(acc[mt], al[mt], bh);
            }
        }
#pragma unroll
        for (int mt = 0; mt < 2; mt++)
#pragma unroll
            for (int half = 0; half < 2; half++) {
                int v    = mt * 16 + grp + half * 8;
                int key0 = kc * 64 + n0 + 2 * tig;
                float s0 = (acc[mt][half * 2 + 0] + sRS[v * 32 + (key0 & 31)]
                            + sCS[v * 32 + (key0 >> 5)]) * inv;
                int key1 = key0 + 1;
                float s1 = (acc[mt][half * 2 + 1] + sRS[v * 32 + (key1 & 31)]
                            + sCS[v * 32 + (key1 >> 5)]) * inv;
                *reinterpret_cast<float2*>(&sS[v * 1028 + key0]) = make_float2(s0, s1);
            }
    }
    __syncthreads();

    // ---- Softmax per row; write probs ----
    {
        int tx = lane;
        int v0 = w * 4;
        for (int r = 0; r < 4; r++) {
            int v = v0 + r;
            float* rowp = sS + v * 1028;
            float mx = -3.4e38f;
#pragma unroll
            for (int s = 0; s < 32; s++) mx = fmaxf(mx, rowp[tx + 32 * s]);
#pragma unroll
            for (int o = 16; o; o >>= 1) mx = fmaxf(mx, __shfl_xor_sync(0xffffffffu, mx, o));
            float sum = 0.f;
#pragma unroll
            for (int s = 0; s < 32; s++) {
                float e = __expf(rowp[tx + 32 * s] - mx);
                rowp[tx + 32 * s] = e;
                sum += e;
            }
#pragma unroll
            for (int o = 16; o; o >>= 1) sum += __shfl_xor_sync(0xffffffffu, sum, o);
            float rinv = 1.0f / sum;
            float* gp = probs + ((size_t)((b * 32 + u) * 32 + v) * 8 + h) * 1024;
#pragma unroll
            for (int s = 0; s < 32; s++) {
                float pv = rowp[tx + 32 * s] * rinv;
                rowp[tx + 32 * s] = pv;
                if (write_probs) gp[tx + 32 * s] = pv;
            }
        }
    }

    // ---- Context: C[32x128] = P @ X, 16 t-chunks of 64 ----
    int n0c = w << 4;
    float acc2[2][2][4] = {};
    for (int tc = 0; tc < 16; tc++) {
        __syncthreads();
        for (int i = tid; i < 2048; i += 256) {
            int t = i >> 5, d4 = (i & 31) << 2;
            float4 x4 = *reinterpret_cast<const float4*>(
                &g_x[(size_t)(b * 1024 + tc * 64 + t) * 128 + d4]);
            __nv_bfloat16 h0, l0, h1, l1, h2, l2, h3, l3;
            bsplit(x4.x, h0, l0); bsplit(x4.y, h1, l1);
            bsplit(x4.z, h2, l2); bsplit(x4.w, h3, l3);
            int o = t * 136 + d4;
            *reinterpret_cast<__nv_bfloat162*>(&sKh[o])     = __nv_bfloat162(h0, h1);
            *reinterpret_cast<__nv_bfloat162*>(&sKh[o + 2]) = __nv_bfloat162(h2, h3);
            *reinterpret_cast<__nv_bfloat162*>(&sKl[o])     = __nv_bfloat162(l0, l1);
            *reinterpret_cast<__nv_bfloat162*>(&sKl[o + 2]) = __nv_bfloat162(l2, l3);
        }
        for (int i = tid; i < 1024; i += 256) {
            int v = i >> 5, t2 = (i & 31) << 1;
            float p0 = sS[v * 1028 + tc * 64 + t2];
            float p1 = sS[v * 1028 + tc * 64 + t2 + 1];
            __nv_bfloat16 h0, l0, h1, l1;
            bsplit(p0, h0, l0); bsplit(p1, h1, l1);
            *reinterpret_cast<__nv_bfloat162*>(&sPh[v * 72 + t2]) = __nv_bfloat162(h0, h1);
            *reinterpret_cast<__nv_bfloat162*>(&sPl[v * 72 + t2]) = __nv_bfloat162(l0, l1);
        }
        __syncthreads();

#pragma unroll
        for (int k0 = 0; k0 < 64; k0 += 16) {
            unsigned ah[2][4], al[2][4], bh[2][2], bl[2][2];
#pragma unroll
            for (int mt = 0; mt < 2; mt++) {
                uint32_t off = (uint32_t)(((mt * 16 + rowA) * 72 + k0 + colA) * 2);
                ldsm_x4(ah[mt], aPh + off);
                ldsm_x4(al[mt], aPl + off);
            }
#pragma unroll
            for (int nt = 0; nt < 2; nt++) {
                uint32_t bo = (uint32_t)(((k0 + rowT) * 136 + n0c + nt * 8) * 2);
                ldsm_x2t(bh[nt], aKh + bo);
                ldsm_x2t(bl[nt], aKl + bo);
            }
#pragma unroll
            for (int mt = 0; mt < 2; mt++)
#pragma unroll
                for (int nt = 0; nt < 2; nt++) {
                    mma_bf16(acc2[mt][nt], ah[mt], bh[nt]);
                    mma_bf16(acc2[mt][nt], ah[mt], bl[nt]);
                    mma_bf16(acc2[mt][nt], al[mt], bh[nt]);
                }
        }
    }
#pragma unroll
    for (int mt = 0; mt < 2; mt++)
#pragma unroll
        for (int nt = 0; nt < 2; nt++)
#pragma unroll
            for (int half = 0; half < 2; half++) {
                int v   = mt * 16 + grp + half * 8;
                int col = n0c + nt * 8 + 2 * tig;
                float2 cv = make_float2(acc2[mt][nt][half * 2], acc2[mt][nt][half * 2 + 1]);
                *reinterpret_cast<float2*>(
                    &g_ctx[(size_t)(b * 1024 + u * 32 + v) * 1024 + h * 128 + col]) = cv;
            }
}

// ---------------------------------------------------------------------------
// Output projection + bias + residual (scalar)
// ---------------------------------------------------------------------------
__global__ __launch_bounds__(256) void outproj_kernel(const float* __restrict__ Wv,
                                                      const float* __restrict__ bias,
                                                      float* __restrict__ out) {
    extern __shared__ float sm[];
    float* sA = sm;
    float* sW = sm + 4096;
    int row0 = blockIdx.x * 32;
    int tid = threadIdx.x;
    int ty = tid >> 5, tx = tid & 31;
    int t0 = ty * 4;
    float acc[4][4] = {};

    for (int cc = 0; cc < 8; cc++) {
        __syncthreads();
        for (int i = tid; i < 4096; i += 256)
            sA[i] = g_ctx[(size_t)(row0 + (i >> 7)) * 1024 + cc * 128 + (i & 127)];
        for (int i = tid; i < 16384; i += 256) {
            int o = i >> 7, c = i & 127;
            sW[c * 129 + o] = Wv[(size_t)o * 1024 + cc * 128 + c];
        }
        __syncthreads();
#pragma unroll 4
        for (int c = 0; c < 128; c++) {
            float av[4], wv[4];
#pragma unroll
            for (int i = 0; i < 4; i++) av[i] = sA[(t0 + i) * 128 + c];
#pragma unroll
            for (int j = 0; j < 4; j++) wv[j] = sW[c * 129 + tx + 32 * j];
#pragma unroll
            for (int i = 0; i < 4; i++)
#pragma unroll
                for (int j = 0; j < 4; j++) acc[i][j] += av[i] * wv[j];
        }
    }
#pragma unroll
    for (int i = 0; i < 4; i++)
#pragma unroll
        for (int j = 0; j < 4; j++) {
            int o = tx + 32 * j;
            size_t r = (size_t)(row0 + t0 + i);
            out[r * 128 + o] = acc[i][j] + bias[o] + g_x[r * 128 + o];
        }
}

// ---------------------------------------------------------------------------
extern "C" void kernel_launch(void* const* d_in, const int* in_sizes, int n_in,
                              void* d_out, int out_size) {
    const float* hs      = (const float*)d_in[0];
    const float* row_emb = (const float*)d_in[1];
    const float* col_emb = (const float*)d_in[2];
    const float* Wq      = (const float*)d_in[3];
    const float* Wk      = (const float*)d_in[4];
    const float* Wv      = (const float*)d_in[5];
    const float* bv      = (const float*)d_in[6];
    const float* lg      = (const float*)d_in[7];
    const float* lb      = (const float*)d_in[8];

    float* out = (float*)d_out;
    int write_probs = (out_size >= 68157440) ? 1 : 0;
    float* probs = out + 1048576;

    int attn_smem = ATTN_F * 4;               // 218,112 B
    int proj_smem = (4096 + 16512) * 4;       // 82,432 B
    cudaFuncSetAttribute(attn_kernel,    cudaFuncAttributeMaxDynamicSharedMemorySize, attn_smem);
    cudaFuncSetAttribute(proj_kernel,    cudaFuncAttributeMaxDynamicSharedMemorySize, proj_smem);
    cudaFuncSetAttribute(outproj_kernel, cudaFuncAttributeMaxDynamicSharedMemorySize, proj_smem);

    ln_kernel<<<1024, 256>>>(hs, lg, lb);
    proj_kernel<<<dim3(256, 8, 2), 256, proj_smem>>>(Wq, Wk);
    attn_kernel<<<dim3(32, 8, 8), 256, attn_smem>>>(row_emb, col_emb, probs, write_probs);
    outproj_kernel<<<256, 256, proj_smem>>>(Wv, bv, out);
}